// round 1
// baseline (speedup 1.0000x reference)
#include <cuda_runtime.h>
#include <math.h>

// Problem constants (fixed-shape problem)
#define NN   50000
#define EE   800000
#define INF  64
#define HIDF 4
#define OUTF 64
#define KH   256      // HID*IN
#define KTOT 320      // KH + IN (concat feat for fused GEMM)

// Scratch (static __device__ arrays: the allowed scratch mechanism)
__device__ float g_neigh[(size_t)NN * KH];   // [n][k] accumulator (atomics)
__device__ float g_cnt[NN];                  // per-dst edge count (float)
__device__ float g_At[(size_t)KTOT * NN];    // k-major transposed A = [scaled neigh ; feat]

// ---------------------------------------------------------------------------
// Edge kernel: one warp per edge (persistent). Lane owns k = lane*8 .. +7.
// W_sp rows / b_sp hoisted into registers once per warp (constant per lane).
// Scatter via red.global.add.v4.f32 (2 per lane per edge).
// ---------------------------------------------------------------------------
__global__ void __launch_bounds__(256) edge_kernel(
    const float* __restrict__ feat,
    const float* __restrict__ pos,
    const int*   __restrict__ src,
    const int*   __restrict__ dst,
    const float* __restrict__ W_sp,
    const float* __restrict__ b_sp)
{
    const int lane   = threadIdx.x & 31;
    const int warp   = (blockIdx.x * blockDim.x + threadIdx.x) >> 5;
    const int nwarps = (gridDim.x * blockDim.x) >> 5;
    const int k0     = lane * 8;

    float w0[8], w1[8], w2[8], bb[8];
#pragma unroll
    for (int i = 0; i < 8; i++) {
        int k = k0 + i;
        w0[i] = __ldg(&W_sp[k * 3 + 0]);
        w1[i] = __ldg(&W_sp[k * 3 + 1]);
        w2[i] = __ldg(&W_sp[k * 3 + 2]);
        bb[i] = __ldg(&b_sp[k]);
    }

    for (int e = warp; e < EE; e += nwarps) {
        const int s = __ldg(&src[e]);
        const int d = __ldg(&dst[e]);

        const float rx = __ldg(&pos[d * 3 + 0]) - __ldg(&pos[s * 3 + 0]);
        const float ry = __ldg(&pos[d * 3 + 1]) - __ldg(&pos[s * 3 + 1]);
        const float rz = __ldg(&pos[d * 3 + 2]) - __ldg(&pos[s * 3 + 2]);
        const float scal = sqrtf(fmaf(rx, rx, fmaf(ry, ry, rz * rz))) + 1e-7f;
        const float inv  = __fdividef(1.0f, scal);
        const float wsx = (rx + 1.0f) * inv;
        const float wsy = (ry + 1.0f) * inv;
        const float wsz = (rz + 1.0f) * inv;

        const float2 f2 = __ldg(reinterpret_cast<const float2*>(&feat[(size_t)s * INF + lane * 2]));

        float m[8];
#pragma unroll
        for (int i = 0; i < 8; i++) {
            float t = fmaf(wsx, w0[i], fmaf(wsy, w1[i], fmaf(wsz, w2[i], bb[i])));
            t = t > 0.0f ? t : 0.01f * t;                     // leaky_relu(0.01)
            m[i] = t * ((i < 4) ? f2.x : f2.y);               // k>>2 == lane*2 + i/4
        }

        float* p = &g_neigh[(size_t)d * KH + k0];
        asm volatile("red.global.add.v4.f32 [%0], {%1,%2,%3,%4};"
                     :: "l"(p), "f"(m[0]), "f"(m[1]), "f"(m[2]), "f"(m[3]) : "memory");
        asm volatile("red.global.add.v4.f32 [%0], {%1,%2,%3,%4};"
                     :: "l"(p + 4), "f"(m[4]), "f"(m[5]), "f"(m[6]), "f"(m[7]) : "memory");
        if (lane == 0) atomicAdd(&g_cnt[d], 1.0f);
    }
}

// ---------------------------------------------------------------------------
// Transpose kernel: build k-major A_t[320][N]:
//   rows [0,256)  = g_neigh[n][k] * 1/max(cnt[n],1)   (mean aggregation)
//   rows [256,320)= feat[n][k-256]
// 32x32 tile transpose through padded smem; coalesced both sides.
// ---------------------------------------------------------------------------
__global__ void transpose_kernel(const float* __restrict__ feat)
{
    __shared__ float tile[32][33];
    const int n0 = blockIdx.x * 32;
    const int k0 = blockIdx.y * 32;
    const int tx = threadIdx.x;   // 0..31
    const int ty = threadIdx.y;   // 0..7

#pragma unroll
    for (int r = 0; r < 32; r += 8) {
        const int n = n0 + ty + r;
        const int k = k0 + tx;
        float v = 0.0f;
        if (n < NN) {
            v = (k < KH) ? g_neigh[(size_t)n * KH + k]
                         : __ldg(&feat[(size_t)n * INF + (k - KH)]);
        }
        tile[tx][ty + r] = v;
    }
    __syncthreads();

    const int n = n0 + tx;
    float sc = 1.0f;
    if (n < NN) sc = __fdividef(1.0f, fmaxf(g_cnt[n], 1.0f));

#pragma unroll
    for (int r = 0; r < 32; r += 8) {
        const int k = k0 + ty + r;
        if (n < NN) {
            float v = tile[ty + r][tx];
            g_At[(size_t)k * NN + n] = (k < KH) ? v * sc : v;
        }
    }
}

// ---------------------------------------------------------------------------
// Node kernel: fused GEMM  out[n][o] = sum_k At[k][n] * Wc[k][o] + b_neigh[o] + bias[o]
// One thread = one node; 64 fp32 accumulators; Wc (320x64, 80KB) staged in
// dynamic smem, read as warp-uniform LDS.128 (broadcast, conflict-free).
// At reads are fully coalesced (k-major).
// ---------------------------------------------------------------------------
__global__ void __launch_bounds__(256, 2) node_kernel(
    const float* __restrict__ W_self,
    const float* __restrict__ W_neigh,
    const float* __restrict__ b_neigh,
    const float* __restrict__ bias,
    float* __restrict__ out)
{
    extern __shared__ float Wc[];   // [KTOT][OUTF]
    const int tid = threadIdx.x;

    for (int idx = tid; idx < KTOT * OUTF; idx += blockDim.x) {
        const int k = idx >> 6;
        const int o = idx & 63;
        Wc[idx] = (k < KH) ? __ldg(&W_neigh[(size_t)o * KH + k])
                           : __ldg(&W_self[(size_t)o * INF + (k - KH)]);
    }
    __syncthreads();

    const int n = blockIdx.x * blockDim.x + tid;
    if (n >= NN) return;

    float acc[64];
#pragma unroll
    for (int o = 0; o < 64; o++) acc[o] = __ldg(&b_neigh[o]) + __ldg(&bias[o]);

    for (int k = 0; k < KTOT; k += 4) {
        const float a0 = __ldg(&g_At[(size_t)(k + 0) * NN + n]);
        const float a1 = __ldg(&g_At[(size_t)(k + 1) * NN + n]);
        const float a2 = __ldg(&g_At[(size_t)(k + 2) * NN + n]);
        const float a3 = __ldg(&g_At[(size_t)(k + 3) * NN + n]);
        const float4* w0 = reinterpret_cast<const float4*>(&Wc[(k + 0) * OUTF]);
        const float4* w1 = reinterpret_cast<const float4*>(&Wc[(k + 1) * OUTF]);
        const float4* w2 = reinterpret_cast<const float4*>(&Wc[(k + 2) * OUTF]);
        const float4* w3 = reinterpret_cast<const float4*>(&Wc[(k + 3) * OUTF]);
#pragma unroll
        for (int oq = 0; oq < 16; oq++) {
            const float4 x0 = w0[oq], x1 = w1[oq], x2 = w2[oq], x3 = w3[oq];
            acc[4 * oq + 0] = fmaf(a0, x0.x, fmaf(a1, x1.x, fmaf(a2, x2.x, fmaf(a3, x3.x, acc[4 * oq + 0]))));
            acc[4 * oq + 1] = fmaf(a0, x0.y, fmaf(a1, x1.y, fmaf(a2, x2.y, fmaf(a3, x3.y, acc[4 * oq + 1]))));
            acc[4 * oq + 2] = fmaf(a0, x0.z, fmaf(a1, x1.z, fmaf(a2, x2.z, fmaf(a3, x3.z, acc[4 * oq + 2]))));
            acc[4 * oq + 3] = fmaf(a0, x0.w, fmaf(a1, x1.w, fmaf(a2, x2.w, fmaf(a3, x3.w, acc[4 * oq + 3]))));
        }
    }

    float4* op = reinterpret_cast<float4*>(&out[(size_t)n * OUTF]);
#pragma unroll
    for (int oq = 0; oq < 16; oq++)
        op[oq] = make_float4(acc[4 * oq + 0], acc[4 * oq + 1], acc[4 * oq + 2], acc[4 * oq + 3]);
}

// ---------------------------------------------------------------------------
// Launch
// ---------------------------------------------------------------------------
extern "C" void kernel_launch(void* const* d_in, const int* in_sizes, int n_in,
                              void* d_out, int out_size)
{
    const float* feat    = (const float*)d_in[0];
    const float* pos     = (const float*)d_in[1];
    const int*   src     = (const int*)  d_in[2];
    const int*   dst     = (const int*)  d_in[3];
    const float* W_self  = (const float*)d_in[4];
    const float* W_sp    = (const float*)d_in[5];
    const float* b_sp    = (const float*)d_in[6];
    const float* W_neigh = (const float*)d_in[7];
    const float* b_neigh = (const float*)d_in[8];
    const float* bias    = (const float*)d_in[9];
    float* out = (float*)d_out;

    void* p_neigh = nullptr;
    void* p_cnt   = nullptr;
    cudaGetSymbolAddress(&p_neigh, g_neigh);
    cudaGetSymbolAddress(&p_cnt, g_cnt);
    cudaMemsetAsync(p_neigh, 0, (size_t)NN * KH * sizeof(float), 0);
    cudaMemsetAsync(p_cnt, 0, (size_t)NN * sizeof(float), 0);

    // Edge phase: persistent, 1184 blocks x 256 threads (9472 warps)
    edge_kernel<<<1184, 256>>>(feat, pos, src, dst, W_sp, b_sp);

    // Transpose + mean-scale + feat concat
    dim3 tgrid((NN + 31) / 32, KTOT / 32);
    transpose_kernel<<<tgrid, dim3(32, 8)>>>(feat);

    // Node GEMM: 80KB dynamic smem
    const int smem = KTOT * OUTF * (int)sizeof(float);
    cudaFuncSetAttribute(node_kernel, cudaFuncAttributeMaxDynamicSharedMemorySize, smem);
    node_kernel<<<(NN + 255) / 256, 256, smem>>>(W_self, W_neigh, b_neigh, bias, out);
}

// round 2
// speedup vs baseline: 1.1733x; 1.1733x over previous
#include <cuda_runtime.h>
#include <math.h>

#define NN   50000
#define EE   800000
#define INF  64
#define HIDF 4
#define OUTF 64
#define KH   256      // HID*IN
#define KTOT 320      // KH + IN

// Scratch
__device__ float g_neigh[(size_t)NN * KH];   // [n][k], mean-scaled, written once
__device__ float g_At[(size_t)KTOT * NN];    // k-major A = [neigh ; feat]
__device__ int   g_deg[NN];
__device__ int   g_rowstart[NN + 1];
__device__ int   g_cursor[NN];
__device__ float4 g_ws[EE];                  // {wsx, wsy, wsz, bitcast(src)} per CSR slot

// ---------------------------------------------------------------------------
// 1) Degree histogram
// ---------------------------------------------------------------------------
__global__ void hist_kernel(const int* __restrict__ dst)
{
    int e = blockIdx.x * blockDim.x + threadIdx.x;
    if (e < EE) atomicAdd(&g_deg[__ldg(&dst[e])], 1);
}

// ---------------------------------------------------------------------------
// 2) Exclusive prefix sum over 50K degrees (single block, 1024 threads)
//    Writes g_rowstart and g_cursor (scatter cursors).
// ---------------------------------------------------------------------------
__global__ void scan_kernel()
{
    __shared__ int partial[1024];
    const int T = 1024;
    const int chunk = (NN + T - 1) / T;       // 49
    const int t = threadIdx.x;
    const int base = t * chunk;

    int sum = 0;
    for (int i = 0; i < chunk; i++) {
        int idx = base + i;
        if (idx < NN) sum += g_deg[idx];
    }
    partial[t] = sum;
    __syncthreads();

    for (int off = 1; off < T; off <<= 1) {
        int v = 0;
        if (t >= off) v = partial[t - off];
        __syncthreads();
        partial[t] += v;
        __syncthreads();
    }

    int run = (t > 0) ? partial[t - 1] : 0;
    for (int i = 0; i < chunk; i++) {
        int idx = base + i;
        if (idx < NN) {
            g_rowstart[idx] = run;
            g_cursor[idx]   = run;
            run += g_deg[idx];
        }
    }
    if (t == T - 1) g_rowstart[NN] = run;
}

// ---------------------------------------------------------------------------
// 3) Scatter: compute spatial weights once per edge, drop {ws, src} into the
//    dst bucket. One small atomic per edge instead of 256 f32 atomics.
// ---------------------------------------------------------------------------
__global__ void __launch_bounds__(256) scatter_kernel(
    const float* __restrict__ pos,
    const int*   __restrict__ src,
    const int*   __restrict__ dst)
{
    int e = blockIdx.x * blockDim.x + threadIdx.x;
    if (e >= EE) return;
    const int s = __ldg(&src[e]);
    const int d = __ldg(&dst[e]);

    const float rx = __ldg(&pos[d * 3 + 0]) - __ldg(&pos[s * 3 + 0]);
    const float ry = __ldg(&pos[d * 3 + 1]) - __ldg(&pos[s * 3 + 1]);
    const float rz = __ldg(&pos[d * 3 + 2]) - __ldg(&pos[s * 3 + 2]);
    const float scal = sqrtf(fmaf(rx, rx, fmaf(ry, ry, rz * rz))) + 1e-7f;
    const float inv  = __fdividef(1.0f, scal);

    const int p = atomicAdd(&g_cursor[d], 1);
    g_ws[p] = make_float4((rx + 1.0f) * inv, (ry + 1.0f) * inv,
                          (rz + 1.0f) * inv, __int_as_float(s));
}

// ---------------------------------------------------------------------------
// 4) Aggregate: one warp per node. Lane owns k = lane*8..+7. Accumulate all
//    edges in registers, scale by 1/deg, write the node row once. No atomics.
// ---------------------------------------------------------------------------
__global__ void __launch_bounds__(256) aggregate_kernel(
    const float* __restrict__ feat,
    const float* __restrict__ W_sp,
    const float* __restrict__ b_sp)
{
    const int lane = threadIdx.x & 31;
    const int node = (blockIdx.x * blockDim.x + threadIdx.x) >> 5;
    if (node >= NN) return;
    const int k0 = lane * 8;

    float w0[8], w1[8], w2[8], bb[8];
#pragma unroll
    for (int i = 0; i < 8; i++) {
        int k = k0 + i;
        w0[i] = __ldg(&W_sp[k * 3 + 0]);
        w1[i] = __ldg(&W_sp[k * 3 + 1]);
        w2[i] = __ldg(&W_sp[k * 3 + 2]);
        bb[i] = __ldg(&b_sp[k]);
    }

    const int start = g_rowstart[node];
    const int end   = g_rowstart[node + 1];

    float acc[8];
#pragma unroll
    for (int i = 0; i < 8; i++) acc[i] = 0.0f;

    float4 nxt;
    if (start < end) nxt = __ldg(&g_ws[start]);

    for (int j = start; j < end; j++) {
        const float4 cur = nxt;
        if (j + 1 < end) nxt = __ldg(&g_ws[j + 1]);   // prefetch next edge
        const int s = __float_as_int(cur.w);
        const float2 f2 = __ldg(reinterpret_cast<const float2*>(&feat[(size_t)s * INF + lane * 2]));
#pragma unroll
        for (int i = 0; i < 8; i++) {
            float t = fmaf(cur.x, w0[i], fmaf(cur.y, w1[i], fmaf(cur.z, w2[i], bb[i])));
            t = t > 0.0f ? t : 0.01f * t;
            acc[i] = fmaf(t, (i < 4) ? f2.x : f2.y, acc[i]);
        }
    }

    const float sc = (end > start) ? __fdividef(1.0f, (float)(end - start)) : 0.0f;
    float4* p = reinterpret_cast<float4*>(&g_neigh[(size_t)node * KH + k0]);
    p[0] = make_float4(acc[0] * sc, acc[1] * sc, acc[2] * sc, acc[3] * sc);
    p[1] = make_float4(acc[4] * sc, acc[5] * sc, acc[6] * sc, acc[7] * sc);
}

// ---------------------------------------------------------------------------
// 5) Transpose to k-major A_t[320][N]: rows [0,256) = g_neigh (already mean-
//    scaled), rows [256,320) = feat. Coalesced both sides via padded smem.
// ---------------------------------------------------------------------------
__global__ void transpose_kernel(const float* __restrict__ feat)
{
    __shared__ float tile[32][33];
    const int n0 = blockIdx.x * 32;
    const int k0 = blockIdx.y * 32;
    const int tx = threadIdx.x;
    const int ty = threadIdx.y;

#pragma unroll
    for (int r = 0; r < 32; r += 8) {
        const int n = n0 + ty + r;
        const int k = k0 + tx;
        float v = 0.0f;
        if (n < NN) {
            v = (k < KH) ? g_neigh[(size_t)n * KH + k]
                         : __ldg(&feat[(size_t)n * INF + (k - KH)]);
        }
        tile[tx][ty + r] = v;
    }
    __syncthreads();

    const int n = n0 + tx;
#pragma unroll
    for (int r = 0; r < 32; r += 8) {
        const int k = k0 + ty + r;
        if (n < NN) g_At[(size_t)k * NN + n] = tile[ty + r][tx];
    }
}

// ---------------------------------------------------------------------------
// 6) Node GEMM: out[n][o] = sum_k At[k][n]*Wc[k][o] + b_neigh[o] + bias[o].
//    512-thread blocks -> 98 blocks -> single wave on 148 SMs.
// ---------------------------------------------------------------------------
__global__ void __launch_bounds__(512, 1) node_kernel(
    const float* __restrict__ W_self,
    const float* __restrict__ W_neigh,
    const float* __restrict__ b_neigh,
    const float* __restrict__ bias,
    float* __restrict__ out)
{
    extern __shared__ float Wc[];   // [KTOT][OUTF] = 80KB
    const int tid = threadIdx.x;

    for (int idx = tid; idx < KTOT * OUTF; idx += blockDim.x) {
        const int k = idx >> 6;
        const int o = idx & 63;
        Wc[idx] = (k < KH) ? __ldg(&W_neigh[(size_t)o * KH + k])
                           : __ldg(&W_self[(size_t)o * INF + (k - KH)]);
    }
    __syncthreads();

    const int n = blockIdx.x * blockDim.x + tid;
    if (n >= NN) return;

    float acc[64];
#pragma unroll
    for (int o = 0; o < 64; o++) acc[o] = __ldg(&b_neigh[o]) + __ldg(&bias[o]);

    for (int k = 0; k < KTOT; k += 4) {
        const float a0 = __ldg(&g_At[(size_t)(k + 0) * NN + n]);
        const float a1 = __ldg(&g_At[(size_t)(k + 1) * NN + n]);
        const float a2 = __ldg(&g_At[(size_t)(k + 2) * NN + n]);
        const float a3 = __ldg(&g_At[(size_t)(k + 3) * NN + n]);
        const float4* w0 = reinterpret_cast<const float4*>(&Wc[(k + 0) * OUTF]);
        const float4* w1 = reinterpret_cast<const float4*>(&Wc[(k + 1) * OUTF]);
        const float4* w2 = reinterpret_cast<const float4*>(&Wc[(k + 2) * OUTF]);
        const float4* w3 = reinterpret_cast<const float4*>(&Wc[(k + 3) * OUTF]);
#pragma unroll
        for (int oq = 0; oq < 16; oq++) {
            const float4 x0 = w0[oq], x1 = w1[oq], x2 = w2[oq], x3 = w3[oq];
            acc[4 * oq + 0] = fmaf(a0, x0.x, fmaf(a1, x1.x, fmaf(a2, x2.x, fmaf(a3, x3.x, acc[4 * oq + 0]))));
            acc[4 * oq + 1] = fmaf(a0, x0.y, fmaf(a1, x1.y, fmaf(a2, x2.y, fmaf(a3, x3.y, acc[4 * oq + 1]))));
            acc[4 * oq + 2] = fmaf(a0, x0.z, fmaf(a1, x1.z, fmaf(a2, x2.z, fmaf(a3, x3.z, acc[4 * oq + 2]))));
            acc[4 * oq + 3] = fmaf(a0, x0.w, fmaf(a1, x1.w, fmaf(a2, x2.w, fmaf(a3, x3.w, acc[4 * oq + 3]))));
        }
    }

    float4* op = reinterpret_cast<float4*>(&out[(size_t)n * OUTF]);
#pragma unroll
    for (int oq = 0; oq < 16; oq++)
        op[oq] = make_float4(acc[4 * oq + 0], acc[4 * oq + 1], acc[4 * oq + 2], acc[4 * oq + 3]);
}

// ---------------------------------------------------------------------------
// Launch
// ---------------------------------------------------------------------------
extern "C" void kernel_launch(void* const* d_in, const int* in_sizes, int n_in,
                              void* d_out, int out_size)
{
    const float* feat    = (const float*)d_in[0];
    const float* pos     = (const float*)d_in[1];
    const int*   src     = (const int*)  d_in[2];
    const int*   dst     = (const int*)  d_in[3];
    const float* W_self  = (const float*)d_in[4];
    const float* W_sp    = (const float*)d_in[5];
    const float* b_sp    = (const float*)d_in[6];
    const float* W_neigh = (const float*)d_in[7];
    const float* b_neigh = (const float*)d_in[8];
    const float* bias    = (const float*)d_in[9];
    float* out = (float*)d_out;

    void* p_deg = nullptr;
    cudaGetSymbolAddress(&p_deg, g_deg);
    cudaMemsetAsync(p_deg, 0, NN * sizeof(int), 0);

    hist_kernel<<<(EE + 255) / 256, 256>>>(dst);
    scan_kernel<<<1, 1024>>>();
    scatter_kernel<<<(EE + 255) / 256, 256>>>(pos, src, dst);
    aggregate_kernel<<<(NN * 32 + 255) / 256, 256>>>(feat, W_sp, b_sp);

    dim3 tgrid((NN + 31) / 32, KTOT / 32);
    transpose_kernel<<<tgrid, dim3(32, 8)>>>(feat);

    const int smem = KTOT * OUTF * (int)sizeof(float);
    cudaFuncSetAttribute(node_kernel, cudaFuncAttributeMaxDynamicSharedMemorySize, smem);
    node_kernel<<<(NN + 511) / 512, 512, smem>>>(W_self, W_neigh, b_neigh, bias, out);
}

// round 3
// speedup vs baseline: 1.5082x; 1.2854x over previous
#include <cuda_runtime.h>
#include <math.h>

#define NN   50000
#define EE   800000
#define INF  64
#define HIDF 4
#define OUTF 64
#define KH   256      // HID*IN
#define KTOT 320      // KH + IN
#define TM   128      // GEMM node tile

// Scratch
__device__ float  g_neigh[(size_t)NN * KH];   // [n][k], mean-scaled
__device__ int    g_deg[NN];
__device__ int    g_rowstart[NN + 1];
__device__ int    g_cursor[NN];
__device__ float4 g_ws[EE];                   // {wsx, wsy, wsz, bitcast(src)}
__device__ float  g_Wc[KTOT * OUTF];          // k-major combined weights [k][o]

// ---------------------------------------------------------------------------
// 1) Degree histogram
// ---------------------------------------------------------------------------
__global__ void hist_kernel(const int* __restrict__ dst)
{
    int e = blockIdx.x * blockDim.x + threadIdx.x;
    if (e < EE) atomicAdd(&g_deg[__ldg(&dst[e])], 1);
}

// ---------------------------------------------------------------------------
// 1b) Weight prep: g_Wc[k][o] = (k<KH ? W_neigh[o][k] : W_self[o][k-KH])
// ---------------------------------------------------------------------------
__global__ void wprep_kernel(const float* __restrict__ W_self,
                             const float* __restrict__ W_neigh)
{
    int idx = blockIdx.x * blockDim.x + threadIdx.x;   // = k*64 + o
    if (idx >= KTOT * OUTF) return;
    const int k = idx >> 6;
    const int o = idx & 63;
    g_Wc[idx] = (k < KH) ? __ldg(&W_neigh[(size_t)o * KH + k])
                         : __ldg(&W_self[(size_t)o * INF + (k - KH)]);
}

// ---------------------------------------------------------------------------
// 2) Exclusive prefix sum over degrees (single block)
// ---------------------------------------------------------------------------
__global__ void scan_kernel()
{
    __shared__ int partial[1024];
    const int T = 1024;
    const int chunk = (NN + T - 1) / T;
    const int t = threadIdx.x;
    const int base = t * chunk;

    int sum = 0;
    for (int i = 0; i < chunk; i++) {
        int idx = base + i;
        if (idx < NN) sum += g_deg[idx];
    }
    partial[t] = sum;
    __syncthreads();
    for (int off = 1; off < T; off <<= 1) {
        int v = 0;
        if (t >= off) v = partial[t - off];
        __syncthreads();
        partial[t] += v;
        __syncthreads();
    }
    int run = (t > 0) ? partial[t - 1] : 0;
    for (int i = 0; i < chunk; i++) {
        int idx = base + i;
        if (idx < NN) {
            g_rowstart[idx] = run;
            g_cursor[idx]   = run;
            run += g_deg[idx];
        }
    }
    if (t == T - 1) g_rowstart[NN] = run;
}

// ---------------------------------------------------------------------------
// 3) Scatter edges into CSR buckets with precomputed spatial weights
// ---------------------------------------------------------------------------
__global__ void __launch_bounds__(256) scatter_kernel(
    const float* __restrict__ pos,
    const int*   __restrict__ src,
    const int*   __restrict__ dst)
{
    int e = blockIdx.x * blockDim.x + threadIdx.x;
    if (e >= EE) return;
    const int s = __ldg(&src[e]);
    const int d = __ldg(&dst[e]);

    const float rx = __ldg(&pos[d * 3 + 0]) - __ldg(&pos[s * 3 + 0]);
    const float ry = __ldg(&pos[d * 3 + 1]) - __ldg(&pos[s * 3 + 1]);
    const float rz = __ldg(&pos[d * 3 + 2]) - __ldg(&pos[s * 3 + 2]);
    const float scal = sqrtf(fmaf(rx, rx, fmaf(ry, ry, rz * rz))) + 1e-7f;
    const float inv  = __fdividef(1.0f, scal);

    const int p = atomicAdd(&g_cursor[d], 1);
    g_ws[p] = make_float4((rx + 1.0f) * inv, (ry + 1.0f) * inv,
                          (rz + 1.0f) * inv, __int_as_float(s));
}

// ---------------------------------------------------------------------------
// 4) Aggregate: warp per node, lane owns 8 channels, 2 edges per iteration
//    for ILP. leaky_relu(t) == fmaxf(t, 0.01f*t).
// ---------------------------------------------------------------------------
__global__ void __launch_bounds__(256) aggregate_kernel(
    const float* __restrict__ feat,
    const float* __restrict__ W_sp,
    const float* __restrict__ b_sp)
{
    const int lane = threadIdx.x & 31;
    const int node = (blockIdx.x * blockDim.x + threadIdx.x) >> 5;
    if (node >= NN) return;
    const int k0 = lane * 8;

    float w0[8], w1[8], w2[8], bb[8];
#pragma unroll
    for (int i = 0; i < 8; i++) {
        int k = k0 + i;
        w0[i] = __ldg(&W_sp[k * 3 + 0]);
        w1[i] = __ldg(&W_sp[k * 3 + 1]);
        w2[i] = __ldg(&W_sp[k * 3 + 2]);
        bb[i] = __ldg(&b_sp[k]);
    }

    const int start = g_rowstart[node];
    const int end   = g_rowstart[node + 1];

    float acc[8];
#pragma unroll
    for (int i = 0; i < 8; i++) acc[i] = 0.0f;

    int j = start;
    for (; j + 2 <= end; j += 2) {
        const float4 wa = __ldg(&g_ws[j]);
        const float4 wb = __ldg(&g_ws[j + 1]);
        const int sa = __float_as_int(wa.w);
        const int sb = __float_as_int(wb.w);
        const float2 fa = __ldg(reinterpret_cast<const float2*>(&feat[(size_t)sa * INF + lane * 2]));
        const float2 fb = __ldg(reinterpret_cast<const float2*>(&feat[(size_t)sb * INF + lane * 2]));
#pragma unroll
        for (int i = 0; i < 8; i++) {
            float ta = fmaf(wa.x, w0[i], fmaf(wa.y, w1[i], fmaf(wa.z, w2[i], bb[i])));
            float tb = fmaf(wb.x, w0[i], fmaf(wb.y, w1[i], fmaf(wb.z, w2[i], bb[i])));
            ta = fmaxf(ta, 0.01f * ta);
            tb = fmaxf(tb, 0.01f * tb);
            acc[i] = fmaf(ta, (i < 4) ? fa.x : fa.y, acc[i]);
            acc[i] = fmaf(tb, (i < 4) ? fb.x : fb.y, acc[i]);
        }
    }
    if (j < end) {
        const float4 wa = __ldg(&g_ws[j]);
        const int sa = __float_as_int(wa.w);
        const float2 fa = __ldg(reinterpret_cast<const float2*>(&feat[(size_t)sa * INF + lane * 2]));
#pragma unroll
        for (int i = 0; i < 8; i++) {
            float ta = fmaf(wa.x, w0[i], fmaf(wa.y, w1[i], fmaf(wa.z, w2[i], bb[i])));
            ta = fmaxf(ta, 0.01f * ta);
            acc[i] = fmaf(ta, (i < 4) ? fa.x : fa.y, acc[i]);
        }
    }

    const float sc = (end > start) ? __fdividef(1.0f, (float)(end - start)) : 0.0f;
    float4* p = reinterpret_cast<float4*>(&g_neigh[(size_t)node * KH + k0]);
    p[0] = make_float4(acc[0] * sc, acc[1] * sc, acc[2] * sc, acc[3] * sc);
    p[1] = make_float4(acc[4] * sc, acc[5] * sc, acc[6] * sc, acc[7] * sc);
}

// ---------------------------------------------------------------------------
// 5) Fused node GEMM (no transpose):
//    out[n][o] = sum_k A[n][k] * Wc[k][o] + b_neigh[o] + bias[o]
//    A = [g_neigh | feat] row-major, staged per 32-k chunk into smem (As[k][n]).
//    Block: 128 nodes x 64 outs, 256 threads, each thread 4n x 8o.
// ---------------------------------------------------------------------------
__global__ void __launch_bounds__(256, 2) gemm_kernel(
    const float* __restrict__ feat,
    const float* __restrict__ b_neigh,
    const float* __restrict__ bias,
    float* __restrict__ out)
{
    __shared__ float Ws[KTOT * OUTF];    // 80 KB, [k][o]
    __shared__ float As[32][TM + 4];     // 16.9 KB, [k][n]

    const int t  = threadIdx.x;
    const int n0 = blockIdx.x * TM;
    const int tn = t & 31;               // node group (4 nodes)
    const int to = t >> 5;               // out group (8 outs)

    // Load full combined weight matrix (coalesced, conflict-free)
    for (int idx = t; idx < KTOT * OUTF; idx += 256)
        Ws[idx] = __ldg(&g_Wc[idx]);

    float bo[8];
#pragma unroll
    for (int j = 0; j < 8; j++)
        bo[j] = __ldg(&b_neigh[to * 8 + j]) + __ldg(&bias[to * 8 + j]);

    float acc[4][8];
#pragma unroll
    for (int i = 0; i < 4; i++)
#pragma unroll
        for (int j = 0; j < 8; j++) acc[i][j] = 0.0f;

    // Per-thread A-tile load mapping: kq = t%8 (float4 of k), nb = t/8 (+32*r)
    const int kq = t & 7;
    const int nb = t >> 3;

    for (int kc = 0; kc < KTOT; kc += 32) {
        __syncthreads();
#pragma unroll
        for (int r = 0; r < 4; r++) {
            const int n = n0 + nb + 32 * r;
            float4 v = make_float4(0.f, 0.f, 0.f, 0.f);
            if (n < NN) {
                if (kc < KH)
                    v = __ldg(reinterpret_cast<const float4*>(&g_neigh[(size_t)n * KH + kc + 4 * kq]));
                else
                    v = __ldg(reinterpret_cast<const float4*>(&feat[(size_t)n * INF + (kc - KH) + 4 * kq]));
            }
            As[4 * kq + 0][nb + 32 * r] = v.x;
            As[4 * kq + 1][nb + 32 * r] = v.y;
            As[4 * kq + 2][nb + 32 * r] = v.z;
            As[4 * kq + 3][nb + 32 * r] = v.w;
        }
        __syncthreads();

#pragma unroll
        for (int k = 0; k < 32; k++) {
            const float4 a  = *reinterpret_cast<const float4*>(&As[k][4 * tn]);
            const float4 b0 = *reinterpret_cast<const float4*>(&Ws[(kc + k) * OUTF + 8 * to]);
            const float4 b1 = *reinterpret_cast<const float4*>(&Ws[(kc + k) * OUTF + 8 * to + 4]);
            const float av[4] = {a.x, a.y, a.z, a.w};
            const float bv[8] = {b0.x, b0.y, b0.z, b0.w, b1.x, b1.y, b1.z, b1.w};
#pragma unroll
            for (int i = 0; i < 4; i++)
#pragma unroll
                for (int j = 0; j < 8; j++)
                    acc[i][j] = fmaf(av[i], bv[j], acc[i][j]);
        }
    }

#pragma unroll
    for (int i = 0; i < 4; i++) {
        const int n = n0 + 4 * tn + i;
        if (n < NN) {
            float4* op = reinterpret_cast<float4*>(&out[(size_t)n * OUTF + 8 * to]);
            op[0] = make_float4(acc[i][0] + bo[0], acc[i][1] + bo[1],
                                acc[i][2] + bo[2], acc[i][3] + bo[3]);
            op[1] = make_float4(acc[i][4] + bo[4], acc[i][5] + bo[5],
                                acc[i][6] + bo[6], acc[i][7] + bo[7]);
        }
    }
}

// ---------------------------------------------------------------------------
// Launch
// ---------------------------------------------------------------------------
extern "C" void kernel_launch(void* const* d_in, const int* in_sizes, int n_in,
                              void* d_out, int out_size)
{
    const float* feat    = (const float*)d_in[0];
    const float* pos     = (const float*)d_in[1];
    const int*   src     = (const int*)  d_in[2];
    const int*   dst     = (const int*)  d_in[3];
    const float* W_self  = (const float*)d_in[4];
    const float* W_sp    = (const float*)d_in[5];
    const float* b_sp    = (const float*)d_in[6];
    const float* W_neigh = (const float*)d_in[7];
    const float* b_neigh = (const float*)d_in[8];
    const float* bias    = (const float*)d_in[9];
    float* out = (float*)d_out;

    void* p_deg = nullptr;
    cudaGetSymbolAddress(&p_deg, g_deg);
    cudaMemsetAsync(p_deg, 0, NN * sizeof(int), 0);

    hist_kernel<<<(EE + 255) / 256, 256>>>(dst);
    wprep_kernel<<<(KTOT * OUTF + 255) / 256, 256>>>(W_self, W_neigh);
    scan_kernel<<<1, 1024>>>();
    scatter_kernel<<<(EE + 255) / 256, 256>>>(pos, src, dst);
    aggregate_kernel<<<(NN * 32 + 255) / 256, 256>>>(feat, W_sp, b_sp);
    gemm_kernel<<<(NN + TM - 1) / TM, 256>>>(feat, b_neigh, bias, out);
}

// round 5
// speedup vs baseline: 1.7898x; 1.1867x over previous
#include <cuda_runtime.h>
#include <cuda_bf16.h>
#include <math.h>
#include <stdint.h>

#define NN   50000
#define EE   800000
#define INF  64
#define OUTF 64
#define KH   256      // HID*IN
#define KTOT 320      // KH + IN
#define NKC  20       // K chunks of 16

// ---------------------------------------------------------------------------
// Scratch (__device__ globals)
// ---------------------------------------------------------------------------
__device__ float  g_neigh[(size_t)NN * KH];   // [n][k], mean-scaled
__device__ int    g_deg[NN];
__device__ int    g_rowstart[NN + 1];
__device__ int    g_cursor[NN];
__device__ float4 g_ws[EE];                   // {wsx, wsy, wsz, bitcast(src)}
__device__ uint4  g_Wfrag[NKC * 8 * 32];      // prepacked B frags {Bh0,Bh1,Bl0,Bl1}
__device__ float  g_bsum[OUTF];               // b_neigh + bias

// ---------------------------------------------------------------------------
// mma helpers
// ---------------------------------------------------------------------------
#define MMA_BF16(d, a0, a1, a2, a3, b0, b1)                                   \
    asm volatile("mma.sync.aligned.m16n8k16.row.col.f32.bf16.bf16.f32 "       \
                 "{%0,%1,%2,%3}, {%4,%5,%6,%7}, {%8,%9}, {%0,%1,%2,%3};"      \
                 : "+f"((d)[0]), "+f"((d)[1]), "+f"((d)[2]), "+f"((d)[3])     \
                 : "r"(a0), "r"(a1), "r"(a2), "r"(a3), "r"(b0), "r"(b1))

__device__ __forceinline__ uint32_t pk_hi(float2 v, float2& res) {
    __nv_bfloat162 h = __float22bfloat162_rn(v);
    float2 hf = __bfloat1622float2(h);
    res = make_float2(v.x - hf.x, v.y - hf.y);
    return *reinterpret_cast<uint32_t*>(&h);
}
__device__ __forceinline__ uint32_t pk(float2 v) {
    __nv_bfloat162 h = __float22bfloat162_rn(v);
    return *reinterpret_cast<uint32_t*>(&h);
}

// ---------------------------------------------------------------------------
// 1) Degree histogram
// ---------------------------------------------------------------------------
__global__ void hist_kernel(const int* __restrict__ dst)
{
    int e = blockIdx.x * blockDim.x + threadIdx.x;
    if (e < EE) atomicAdd(&g_deg[__ldg(&dst[e])], 1);
}

// ---------------------------------------------------------------------------
// 1b) Weight prep: build per-thread mma B fragments (bf16 hi/lo) in the exact
//     m16n8k16 .col register layout, plus bsum. One thread per uint4.
//     idx -> kc = idx/256, nc = (idx/32)%8, lane = idx%32.
//     B elem (k, n): k = kc*16 + (lane%4)*2 + {0,1} (+8 for reg1), n = nc*8 + lane/4.
// ---------------------------------------------------------------------------
__global__ void wprep_kernel(const float* __restrict__ W_self,
                             const float* __restrict__ W_neigh,
                             const float* __restrict__ b_neigh,
                             const float* __restrict__ bias)
{
    int idx = blockIdx.x * blockDim.x + threadIdx.x;
    if (idx < OUTF) g_bsum[idx] = __ldg(&b_neigh[idx]) + __ldg(&bias[idx]);
    if (idx >= NKC * 8 * 32) return;

    const int lane = idx & 31;
    const int nc   = (idx >> 5) & 7;
    const int kc   = idx >> 8;
    const int n    = nc * 8 + (lane >> 2);
    const int k0   = kc * 16 + (lane & 3) * 2;

    float v[4];
#pragma unroll
    for (int r = 0; r < 2; r++)
#pragma unroll
        for (int j = 0; j < 2; j++) {
            const int k = k0 + r * 8 + j;
            v[r * 2 + j] = (k < KH) ? __ldg(&W_neigh[(size_t)n * KH + k])
                                    : __ldg(&W_self[(size_t)n * INF + (k - KH)]);
        }

    float2 r0, r1;
    uint4 q;
    q.x = pk_hi(make_float2(v[0], v[1]), r0);
    q.y = pk_hi(make_float2(v[2], v[3]), r1);
    q.z = pk(r0);
    q.w = pk(r1);
    g_Wfrag[idx] = q;
}

// ---------------------------------------------------------------------------
// 2) Exclusive prefix sum over degrees (single block)
// ---------------------------------------------------------------------------
__global__ void scan_kernel()
{
    __shared__ int partial[1024];
    const int T = 1024;
    const int chunk = (NN + T - 1) / T;
    const int t = threadIdx.x;
    const int base = t * chunk;

    int sum = 0;
    for (int i = 0; i < chunk; i++) {
        int idx = base + i;
        if (idx < NN) sum += g_deg[idx];
    }
    partial[t] = sum;
    __syncthreads();
    for (int off = 1; off < T; off <<= 1) {
        int v = 0;
        if (t >= off) v = partial[t - off];
        __syncthreads();
        partial[t] += v;
        __syncthreads();
    }
    int run = (t > 0) ? partial[t - 1] : 0;
    for (int i = 0; i < chunk; i++) {
        int idx = base + i;
        if (idx < NN) {
            g_rowstart[idx] = run;
            g_cursor[idx]   = run;
            run += g_deg[idx];
        }
    }
    if (t == T - 1) g_rowstart[NN] = run;
}

// ---------------------------------------------------------------------------
// 3) Scatter edges into CSR buckets with precomputed spatial weights
// ---------------------------------------------------------------------------
__global__ void __launch_bounds__(256) scatter_kernel(
    const float* __restrict__ pos,
    const int*   __restrict__ src,
    const int*   __restrict__ dst)
{
    int e = blockIdx.x * blockDim.x + threadIdx.x;
    if (e >= EE) return;
    const int s = __ldg(&src[e]);
    const int d = __ldg(&dst[e]);

    const float rx = __ldg(&pos[d * 3 + 0]) - __ldg(&pos[s * 3 + 0]);
    const float ry = __ldg(&pos[d * 3 + 1]) - __ldg(&pos[s * 3 + 1]);
    const float rz = __ldg(&pos[d * 3 + 2]) - __ldg(&pos[s * 3 + 2]);
    const float scal = sqrtf(fmaf(rx, rx, fmaf(ry, ry, rz * rz))) + 1e-7f;
    const float inv  = __fdividef(1.0f, scal);

    const int p = atomicAdd(&g_cursor[d], 1);
    g_ws[p] = make_float4((rx + 1.0f) * inv, (ry + 1.0f) * inv,
                          (rz + 1.0f) * inv, __int_as_float(s));
}

// ---------------------------------------------------------------------------
// 4) Aggregate: warp per node, lane owns 8 channels, 2-edge unroll.
// ---------------------------------------------------------------------------
__global__ void __launch_bounds__(256) aggregate_kernel(
    const float* __restrict__ feat,
    const float* __restrict__ W_sp,
    const float* __restrict__ b_sp)
{
    const int lane = threadIdx.x & 31;
    const int node = (blockIdx.x * blockDim.x + threadIdx.x) >> 5;
    if (node >= NN) return;
    const int k0 = lane * 8;

    float w0[8], w1[8], w2[8], bb[8];
#pragma unroll
    for (int i = 0; i < 8; i++) {
        int k = k0 + i;
        w0[i] = __ldg(&W_sp[k * 3 + 0]);
        w1[i] = __ldg(&W_sp[k * 3 + 1]);
        w2[i] = __ldg(&W_sp[k * 3 + 2]);
        bb[i] = __ldg(&b_sp[k]);
    }

    const int start = g_rowstart[node];
    const int end   = g_rowstart[node + 1];

    float acc[8];
#pragma unroll
    for (int i = 0; i < 8; i++) acc[i] = 0.0f;

    int j = start;
    for (; j + 2 <= end; j += 2) {
        const float4 wa = __ldg(&g_ws[j]);
        const float4 wb = __ldg(&g_ws[j + 1]);
        const int sa = __float_as_int(wa.w);
        const int sb = __float_as_int(wb.w);
        const float2 fa = __ldg(reinterpret_cast<const float2*>(&feat[(size_t)sa * INF + lane * 2]));
        const float2 fb = __ldg(reinterpret_cast<const float2*>(&feat[(size_t)sb * INF + lane * 2]));
#pragma unroll
        for (int i = 0; i < 8; i++) {
            float ta = fmaf(wa.x, w0[i], fmaf(wa.y, w1[i], fmaf(wa.z, w2[i], bb[i])));
            float tb = fmaf(wb.x, w0[i], fmaf(wb.y, w1[i], fmaf(wb.z, w2[i], bb[i])));
            ta = fmaxf(ta, 0.01f * ta);
            tb = fmaxf(tb, 0.01f * tb);
            acc[i] = fmaf(ta, (i < 4) ? fa.x : fa.y, acc[i]);
            acc[i] = fmaf(tb, (i < 4) ? fb.x : fb.y, acc[i]);
        }
    }
    if (j < end) {
        const float4 wa = __ldg(&g_ws[j]);
        const int sa = __float_as_int(wa.w);
        const float2 fa = __ldg(reinterpret_cast<const float2*>(&feat[(size_t)sa * INF + lane * 2]));
#pragma unroll
        for (int i = 0; i < 8; i++) {
            float ta = fmaf(wa.x, w0[i], fmaf(wa.y, w1[i], fmaf(wa.z, w2[i], bb[i])));
            ta = fmaxf(ta, 0.01f * ta);
            acc[i] = fmaf(ta, (i < 4) ? fa.x : fa.y, acc[i]);
        }
    }

    const float sc = (end > start) ? __fdividef(1.0f, (float)(end - start)) : 0.0f;
    float4* p = reinterpret_cast<float4*>(&g_neigh[(size_t)node * KH + k0]);
    p[0] = make_float4(acc[0] * sc, acc[1] * sc, acc[2] * sc, acc[3] * sc);
    p[1] = make_float4(acc[4] * sc, acc[5] * sc, acc[6] * sc, acc[7] * sc);
}

// ---------------------------------------------------------------------------
// 5) Node GEMM via mma.sync bf16 (3-term hi/lo split):
//    out[m][n] = sum_k A[m][k] * W[k][n] + bsum[n],  A = [g_neigh | feat]
//    Warp -> 16x64 tile (8 n-chunks), block = 8 warps = 128 rows, grid 391.
//    A frags from gmem float2s (exact-once), B frags prepacked in g_Wfrag.
// ---------------------------------------------------------------------------
__global__ void __launch_bounds__(256) gemm_kernel(
    const float* __restrict__ feat, float* __restrict__ out)
{
    const int lane = threadIdx.x & 31;
    const int warp = threadIdx.x >> 5;
    const int m    = blockIdx.x * 128 + warp * 16 + (lane >> 2);   // rows m, m+8
    const int kq   = (lane & 3) * 2;

    const bool v0 = (m < NN);
    const bool v1 = (m + 8 < NN);
    const float2 z2 = make_float2(0.f, 0.f);

    float D[8][4];
#pragma unroll
    for (int nc = 0; nc < 8; nc++)
#pragma unroll
        for (int i = 0; i < 4; i++) D[nc][i] = 0.0f;

#pragma unroll 4
    for (int kc = 0; kc < NKC; kc++) {
        // A fragment: (m, kq), (m+8, kq), (m, kq+8), (m+8, kq+8) float2 pairs
        float2 p00, p10, p01, p11;
        if (kc < 16) {
            const int c = kc * 16 + kq;
            const float* r0 = &g_neigh[(size_t)m * KH + c];
            const float* r1 = &g_neigh[(size_t)(m + 8) * KH + c];
            p00 = v0 ? __ldg(reinterpret_cast<const float2*>(r0))     : z2;
            p01 = v0 ? __ldg(reinterpret_cast<const float2*>(r0 + 8)) : z2;
            p10 = v1 ? __ldg(reinterpret_cast<const float2*>(r1))     : z2;
            p11 = v1 ? __ldg(reinterpret_cast<const float2*>(r1 + 8)) : z2;
        } else {
            const int c = (kc - 16) * 16 + kq;
            const float* r0 = &feat[(size_t)m * INF + c];
            const float* r1 = &feat[(size_t)(m + 8) * INF + c];
            p00 = v0 ? __ldg(reinterpret_cast<const float2*>(r0))     : z2;
            p01 = v0 ? __ldg(reinterpret_cast<const float2*>(r0 + 8)) : z2;
            p10 = v1 ? __ldg(reinterpret_cast<const float2*>(r1))     : z2;
            p11 = v1 ? __ldg(reinterpret_cast<const float2*>(r1 + 8)) : z2;
        }
        float2 q00, q10, q01, q11;
        const uint32_t ah0 = pk_hi(p00, q00);
        const uint32_t ah1 = pk_hi(p10, q10);
        const uint32_t ah2 = pk_hi(p01, q01);
        const uint32_t ah3 = pk_hi(p11, q11);
        const uint32_t al0 = pk(q00), al1 = pk(q10), al2 = pk(q01), al3 = pk(q11);

        const uint4* wf = &g_Wfrag[(kc * 8) * 32 + lane];
#pragma unroll
        for (int nc = 0; nc < 8; nc++) {
            const uint4 b = __ldg(wf + nc * 32);
            MMA_BF16(D[nc], ah0, ah1, ah2, ah3, b.x, b.y);   // Ah * Wh
            MMA_BF16(D[nc], al0, al1, al2, al3, b.x, b.y);   // Al * Wh
            MMA_BF16(D[nc], ah0, ah1, ah2, ah3, b.z, b.w);   // Ah * Wl
        }
    }

    // Epilogue: D[nc] = {(m,n),(m,n+1),(m+8,n),(m+8,n+1)} with n = nc*8 + kq
#pragma unroll
    for (int nc = 0; nc < 8; nc++) {
        const int n = nc * 8 + kq;
        const float bx = __ldg(&g_bsum[n]);
        const float by = __ldg(&g_bsum[n + 1]);
        if (v0)
            *reinterpret_cast<float2*>(&out[(size_t)m * OUTF + n]) =
                make_float2(D[nc][0] + bx, D[nc][1] + by);
        if (v1)
            *reinterpret_cast<float2*>(&out[(size_t)(m + 8) * OUTF + n]) =
                make_float2(D[nc][2] + bx, D[nc][3] + by);
    }
}

// ---------------------------------------------------------------------------
// Launch
// ---------------------------------------------------------------------------
extern "C" void kernel_launch(void* const* d_in, const int* in_sizes, int n_in,
                              void* d_out, int out_size)
{
    const float* feat    = (const float*)d_in[0];
    const float* pos     = (const float*)d_in[1];
    const int*   src     = (const int*)  d_in[2];
    const int*   dst     = (const int*)  d_in[3];
    const float* W_self  = (const float*)d_in[4];
    const float* W_sp    = (const float*)d_in[5];
    const float* b_sp    = (const float*)d_in[6];
    const float* W_neigh = (const float*)d_in[7];
    const float* b_neigh = (const float*)d_in[8];
    const float* bias    = (const float*)d_in[9];
    float* out = (float*)d_out;

    void* p_deg = nullptr;
    cudaGetSymbolAddress(&p_deg, g_deg);
    cudaMemsetAsync(p_deg, 0, NN * sizeof(int), 0);

    hist_kernel<<<(EE + 255) / 256, 256>>>(dst);
    wprep_kernel<<<(NKC * 8 * 32 + 255) / 256, 256>>>(W_self, W_neigh, b_neigh, bias);
    scan_kernel<<<1, 1024>>>();
    scatter_kernel<<<(EE + 255) / 256, 256>>>(pos, src, dst);
    aggregate_kernel<<<(NN * 32 + 255) / 256, 256>>>(feat, W_sp, b_sp);
    gemm_kernel<<<(NN + 127) / 128, 256>>>(feat, out);
}